// round 10
// baseline (speedup 1.0000x reference)
#include <cuda_runtime.h>
#include <cuda_fp16.h>
#include <stdint.h>

#define BATCHN 65536
#define NROWS  (BATCHN * 8)
#define NGRP   8192
#define OBSD   114

__device__ __half g_av[(size_t)BATCHN * 128];   // agent values, fp16 (16 MB)

__device__ __forceinline__ float fast_tanh(float x){float y;asm("tanh.approx.f32 %0,%1;":"=f"(y):"f"(x));return y;}
__device__ __forceinline__ float tanh_acc(float x){ return 1.f - __fdividef(2.f, __expf(2.f * x) + 1.f); }
__device__ __forceinline__ uint32_t pack2(float a, float b){ __half2 h = __floats2half2_rn(a, b); return *(uint32_t*)&h; }

__device__ __forceinline__ void mma16(float c[4], uint32_t a0, uint32_t a1, uint32_t a2, uint32_t a3,
                                      uint32_t b0, uint32_t b1){
    asm volatile("mma.sync.aligned.m16n8k16.row.col.f32.f16.f16.f32 "
                 "{%0,%1,%2,%3},{%4,%5,%6,%7},{%8,%9},{%0,%1,%2,%3};"
                 : "+f"(c[0]), "+f"(c[1]), "+f"(c[2]), "+f"(c[3])
                 : "r"(a0), "r"(a1), "r"(a2), "r"(a3), "r"(b0), "r"(b1));
}

// Dual-slab layer: 2 x (16 rows x 128 cols); each B fragment feeds 4 MMAs.
// Wp layout: [(ks*8+ntp)*32+lane] = uint4{frags for nt=2ntp, 2ntp+1}.
template<int KS>
__device__ __forceinline__ void mma_reg2(const uint32_t (&af)[2][KS][4],
                                         const uint4* __restrict__ Wp,
                                         float (&acc)[2][16][4], int lane){
    #pragma unroll
    for (int s = 0; s < 2; s++)
        #pragma unroll
        for (int nt = 0; nt < 16; nt++){
            acc[s][nt][0]=acc[s][nt][1]=acc[s][nt][2]=acc[s][nt][3]=0.f;
        }
    #pragma unroll
    for (int ks = 0; ks < KS; ks++){
        #pragma unroll
        for (int ntp = 0; ntp < 8; ntp++){
            uint4 b = Wp[ks * 256 + ntp * 32 + lane];
            #pragma unroll
            for (int s = 0; s < 2; s++){
                mma16(acc[s][2*ntp],   af[s][ks][0], af[s][ks][1], af[s][ks][2], af[s][ks][3], b.x, b.y);
                mma16(acc[s][2*ntp+1], af[s][ks][0], af[s][ks][1], af[s][ks][2], af[s][ks][3], b.z, b.w);
            }
        }
    }
}

// acc(+bias) -> fast tanh -> repack as next layer's A-fragments (in registers).
__device__ __forceinline__ void transition(const float acc[16][4], uint32_t af[8][4],
                                           const float* __restrict__ bias, int t){
    #pragma unroll
    for (int ks = 0; ks < 8; ks++){
        int c0 = (2*ks) * 8 + 2 * t, c1 = c0 + 8;
        float b00 = bias[c0], b01 = bias[c0 + 1];
        float b10 = bias[c1], b11 = bias[c1 + 1];
        af[ks][0] = pack2(fast_tanh(acc[2*ks][0] + b00),   fast_tanh(acc[2*ks][1] + b01));
        af[ks][1] = pack2(fast_tanh(acc[2*ks][2] + b00),   fast_tanh(acc[2*ks][3] + b01));
        af[ks][2] = pack2(fast_tanh(acc[2*ks+1][0] + b10), fast_tanh(acc[2*ks+1][1] + b11));
        af[ks][3] = pack2(fast_tanh(acc[2*ks+1][2] + b10), fast_tanh(acc[2*ks+1][3] + b11));
    }
}

// Pack W[k][n] (row-major K x 128 fp32) into uint4 B-fragment-pair order.
__device__ __forceinline__ void pack_w4(const float* __restrict__ W, uint4* __restrict__ Wp,
                                        int KS, int K, int tid, int nthr){
    for (int f = tid; f < KS * 8 * 32; f += nthr){
        int ks = f >> 8, ntp = (f >> 5) & 7, lane = f & 31;
        int g = lane >> 2, t = lane & 3;
        int n0 = ntp * 16 + g, n1 = n0 + 8;
        int k0 = ks * 16 + 2 * t, k1 = k0 + 8;
        float a00 = (k0     < K) ? W[(size_t)k0       * 128 + n0] : 0.f;
        float a01 = (k0 + 1 < K) ? W[(size_t)(k0 + 1) * 128 + n0] : 0.f;
        float a10 = (k1     < K) ? W[(size_t)k1       * 128 + n0] : 0.f;
        float a11 = (k1 + 1 < K) ? W[(size_t)(k1 + 1) * 128 + n0] : 0.f;
        float b00 = (k0     < K) ? W[(size_t)k0       * 128 + n1] : 0.f;
        float b01 = (k0 + 1 < K) ? W[(size_t)(k0 + 1) * 128 + n1] : 0.f;
        float b10 = (k1     < K) ? W[(size_t)k1       * 128 + n1] : 0.f;
        float b11 = (k1 + 1 < K) ? W[(size_t)(k1 + 1) * 128 + n1] : 0.f;
        Wp[f] = make_uint4(pack2(a00, a01), pack2(a10, a11), pack2(b00, b01), pack2(b10, b11));
    }
}

// smem offsets (fused)
#define F_W1E  0
#define F_W2E  8192
#define F_W1V  40960
#define F_W2V  73728
#define F_BS   106496
#define F_STG  108544
#define F_SMEM (108544 + 8 * 16 * 40 * 2)   // 118784

// ============================================================================
// FUSED: gather -> embed MLP -> attn -> value MLP -> combine -> AA.
// 256 threads; each warp owns TWO 16-row slabs (4 batches), all 128 cols.
// Barrier-free main loop; lane = g*4 + t.
// ============================================================================
__global__ void __launch_bounds__(256, 1)
fused_ev_kernel(const float* __restrict__ obs,
                const float* __restrict__ eW1, const float* __restrict__ eb1,
                const float* __restrict__ eW2, const float* __restrict__ eb2,
                const float* __restrict__ vW1, const float* __restrict__ vb1,
                const float* __restrict__ vW2, const float* __restrict__ vb2,
                float* __restrict__ AA)
{
    extern __shared__ char sm[];
    uint4* W1E = (uint4*)(sm + F_W1E);
    uint4* W2E = (uint4*)(sm + F_W2E);
    uint4* W1V = (uint4*)(sm + F_W1V);
    uint4* W2V = (uint4*)(sm + F_W2V);
    float* bs  = (float*)(sm + F_BS);

    const int tid = threadIdx.x, w = tid >> 5, lane = tid & 31;
    const int g = lane >> 2, t = lane & 3;

    pack_w4(eW1, W1E, 2, 30, tid, 256);
    pack_w4(eW2, W2E, 8, 128, tid, 256);
    pack_w4(vW1, W1V, 8, 128, tid, 256);
    pack_w4(vW2, W2V, 8, 128, tid, 256);
    if (tid < 128){
        bs[tid] = eb1[tid]; bs[128 + tid] = eb2[tid];
        bs[256 + tid] = vb1[tid]; bs[384 + tid] = vb2[tid];
    }
    __syncthreads();

    __half* stg = (__half*)(sm + F_STG) + w * 16 * 40;
    const float qs = 0.011048543456039806f;   // 1/(8*sqrt(128))
    const int NPAIR = NROWS / 32;             // 16384
    const int step  = gridDim.x * 8;

    for (int pair = blockIdx.x * 8 + w; pair < NPAIR; pair += step){
        uint32_t af1[2][2][4];
        // ---- gather both slabs (reusing the 16x40 stage) ----
        #pragma unroll
        for (int s = 0; s < 2; s++){
            const int row0 = (pair * 2 + s) * 16;
            {
                int r = lane >> 1, q = lane & 1;
                int R = row0 + r;
                const float* sp = obs + (size_t)(R & (BATCHN - 1)) * OBSD;
                const float* np = obs + (size_t)(R >> 3) * OBSD + 18 + (R & 7) * 12;
                uint32_t h[8];
                #pragma unroll
                for (int jj = 0; jj < 8; jj++){
                    int c = q * 16 + 2 * jj;
                    float v0 = (c     < 18) ? sp[c]     : ((c     < 30) ? np[c - 18] : 0.f);
                    float v1 = (c + 1 < 18) ? sp[c + 1] : ((c + 1 < 30) ? np[c - 17] : 0.f);
                    h[jj] = pack2(v0, v1);
                }
                *(uint4*)(stg + r * 40 + q * 16)     = make_uint4(h[0], h[1], h[2], h[3]);
                *(uint4*)(stg + r * 40 + q * 16 + 8) = make_uint4(h[4], h[5], h[6], h[7]);
            }
            __syncwarp();
            const __half* s0 = stg + g * 40;
            const __half* s1 = stg + (g + 8) * 40;
            #pragma unroll
            for (int ks = 0; ks < 2; ks++){
                af1[s][ks][0] = *(const uint32_t*)(s0 + ks * 16 + 2 * t);
                af1[s][ks][1] = *(const uint32_t*)(s1 + ks * 16 + 2 * t);
                af1[s][ks][2] = *(const uint32_t*)(s0 + ks * 16 + 2 * t + 8);
                af1[s][ks][3] = *(const uint32_t*)(s1 + ks * 16 + 2 * t + 8);
            }
            __syncwarp();
        }

        float acc[2][16][4];
        uint32_t af[2][8][4];
        mma_reg2<2>(af1, W1E, acc, lane);                  // embed L1
        #pragma unroll
        for (int s = 0; s < 2; s++) transition(acc[s], af[s], bs, t);
        mma_reg2<8>(af, W2E, acc, lane);                   // embed L2
        #pragma unroll
        for (int s = 0; s < 2; s++) transition(acc[s], af[s], bs + 128, t);  // e

        // ---- attention weights from e (per slab) ----
        float wA[2], wB[2];
        #pragma unroll
        for (int s = 0; s < 2; s++){
            float fa[32];
            #pragma unroll
            for (int ks = 0; ks < 8; ks++){
                float2 u0 = __half22float2(*(__half2*)&af[s][ks][0]);
                float2 u2 = __half22float2(*(__half2*)&af[s][ks][2]);
                fa[4*ks]=u0.x; fa[4*ks+1]=u0.y; fa[4*ks+2]=u2.x; fa[4*ks+3]=u2.y;
            }
            #pragma unroll
            for (int o = 4; o <= 16; o <<= 1)
                #pragma unroll
                for (int i = 0; i < 32; i++) fa[i] += __shfl_xor_sync(0xffffffff, fa[i], o);
            float sA = 0.f;
            #pragma unroll
            for (int ks = 0; ks < 8; ks++){
                float2 u0 = __half22float2(*(__half2*)&af[s][ks][0]);
                float2 u2 = __half22float2(*(__half2*)&af[s][ks][2]);
                sA += fa[4*ks]*u0.x + fa[4*ks+1]*u0.y + fa[4*ks+2]*u2.x + fa[4*ks+3]*u2.y;
            }
            sA *= qs;
            sA += __shfl_xor_sync(0xffffffff, sA, 1);
            sA += __shfl_xor_sync(0xffffffff, sA, 2);
            #pragma unroll
            for (int ks = 0; ks < 8; ks++){
                float2 u1 = __half22float2(*(__half2*)&af[s][ks][1]);
                float2 u3 = __half22float2(*(__half2*)&af[s][ks][3]);
                fa[4*ks]=u1.x; fa[4*ks+1]=u1.y; fa[4*ks+2]=u3.x; fa[4*ks+3]=u3.y;
            }
            #pragma unroll
            for (int o = 4; o <= 16; o <<= 1)
                #pragma unroll
                for (int i = 0; i < 32; i++) fa[i] += __shfl_xor_sync(0xffffffff, fa[i], o);
            float sB = 0.f;
            #pragma unroll
            for (int ks = 0; ks < 8; ks++){
                float2 u1 = __half22float2(*(__half2*)&af[s][ks][1]);
                float2 u3 = __half22float2(*(__half2*)&af[s][ks][3]);
                sB += fa[4*ks]*u1.x + fa[4*ks+1]*u1.y + fa[4*ks+2]*u3.x + fa[4*ks+3]*u3.y;
            }
            sB *= qs;
            sB += __shfl_xor_sync(0xffffffff, sB, 1);
            sB += __shfl_xor_sync(0xffffffff, sB, 2);
            float mxA = sA, mxB = sB;
            #pragma unroll
            for (int o = 4; o <= 16; o <<= 1){
                mxA = fmaxf(mxA, __shfl_xor_sync(0xffffffff, mxA, o));
                mxB = fmaxf(mxB, __shfl_xor_sync(0xffffffff, mxB, o));
            }
            float eA = __expf(sA - mxA), eB = __expf(sB - mxB);
            float uA = eA, uB = eB;
            #pragma unroll
            for (int o = 4; o <= 16; o <<= 1){
                uA += __shfl_xor_sync(0xffffffff, uA, o);
                uB += __shfl_xor_sync(0xffffffff, uB, o);
            }
            wA[s] = eA / uA; wB[s] = eB / uB;
        }

        // ---- value MLP on e ----
        mma_reg2<8>(af, W1V, acc, lane);
        #pragma unroll
        for (int s = 0; s < 2; s++) transition(acc[s], af[s], bs + 256, t);
        mma_reg2<8>(af, W2V, acc, lane);

        // ---- v = tanh_acc(acc+b2); weighted neighbor sum -> AA ----
        #pragma unroll
        for (int s = 0; s < 2; s++){
            #pragma unroll
            for (int nt = 0; nt < 16; nt++){
                int c = nt * 8 + 2 * t;
                float b0 = bs[384 + c], b1 = bs[384 + c + 1];
                acc[s][nt][0] = tanh_acc(acc[s][nt][0] + b0) * wA[s];
                acc[s][nt][1] = tanh_acc(acc[s][nt][1] + b1) * wA[s];
                acc[s][nt][2] = tanh_acc(acc[s][nt][2] + b0) * wB[s];
                acc[s][nt][3] = tanh_acc(acc[s][nt][3] + b1) * wB[s];
            }
            #pragma unroll
            for (int o = 4; o <= 16; o <<= 1)
                #pragma unroll
                for (int nt = 0; nt < 16; nt++){
                    acc[s][nt][0] += __shfl_xor_sync(0xffffffff, acc[s][nt][0], o);
                    acc[s][nt][1] += __shfl_xor_sync(0xffffffff, acc[s][nt][1], o);
                    acc[s][nt][2] += __shfl_xor_sync(0xffffffff, acc[s][nt][2], o);
                    acc[s][nt][3] += __shfl_xor_sync(0xffffffff, acc[s][nt][3], o);
                }
            float* outA = AA + (size_t)((pair * 2 + s) * 2) * 128;
            if (lane < 4){
                #pragma unroll
                for (int nt = 0; nt < 16; nt++)
                    *(float2*)(outA + nt * 8 + 2 * t) = make_float2(acc[s][nt][0], acc[s][nt][1]);
            } else if (lane < 8){
                #pragma unroll
                for (int nt = 0; nt < 16; nt++)
                    *(float2*)(outA + 128 + nt * 8 + 2 * t) = make_float2(acc[s][nt][2], acc[s][nt][3]);
            }
        }
    }
}

// smem offsets (agent)
#define A_W1   0
#define A_W2   32768
#define A_BS   65536
#define A_SMEM 66560

// ============================================================================
// Agent MLP: AA (fp32) -> tanh(128->128) -> tanh(128->128) -> g_av (fp16)
// Dual-slab register-chained.
// ============================================================================
__global__ void __launch_bounds__(256, 1)
agent_kernel(const float* __restrict__ X,
             const float* __restrict__ W1, const float* __restrict__ b1,
             const float* __restrict__ W2, const float* __restrict__ b2,
             __half* __restrict__ Y)
{
    extern __shared__ char sm[];
    uint4* Wp1 = (uint4*)(sm + A_W1);
    uint4* Wp2 = (uint4*)(sm + A_W2);
    float* bs  = (float*)(sm + A_BS);

    const int tid = threadIdx.x, w = tid >> 5, lane = tid & 31;
    const int g = lane >> 2, t = lane & 3;

    pack_w4(W1, Wp1, 8, 128, tid, 256);
    pack_w4(W2, Wp2, 8, 128, tid, 256);
    if (tid < 128){ bs[tid] = b1[tid]; bs[128 + tid] = b2[tid]; }
    __syncthreads();

    const int NPAIR = BATCHN / 32;            // 2048
    const int step  = gridDim.x * 8;

    for (int pair = blockIdx.x * 8 + w; pair < NPAIR; pair += step){
        uint32_t af[2][8][4];
        #pragma unroll
        for (int s = 0; s < 2; s++){
            const int row0 = (pair * 2 + s) * 16;
            const float2* pA = (const float2*)(X + (size_t)(row0 + g) * 128);
            const float2* pB = (const float2*)(X + (size_t)(row0 + g + 8) * 128);
            #pragma unroll
            for (int ks = 0; ks < 8; ks++){
                float2 a0 = pA[ks * 8 + t],     b0v = pB[ks * 8 + t];
                float2 a2 = pA[ks * 8 + t + 4], b2v = pB[ks * 8 + t + 4];
                af[s][ks][0] = pack2(a0.x, a0.y);
                af[s][ks][1] = pack2(b0v.x, b0v.y);
                af[s][ks][2] = pack2(a2.x, a2.y);
                af[s][ks][3] = pack2(b2v.x, b2v.y);
            }
        }
        float acc[2][16][4];
        mma_reg2<8>(af, Wp1, acc, lane);
        #pragma unroll
        for (int s = 0; s < 2; s++) transition(acc[s], af[s], bs, t);
        mma_reg2<8>(af, Wp2, acc, lane);
        #pragma unroll
        for (int s = 0; s < 2; s++){
            const int row0 = (pair * 2 + s) * 16;
            __half* y0 = Y + (size_t)(row0 + g) * 128;
            __half* y1 = Y + (size_t)(row0 + g + 8) * 128;
            #pragma unroll
            for (int nt = 0; nt < 16; nt++){
                int c = nt * 8 + 2 * t;
                float b0 = bs[128 + c], b1v = bs[128 + c + 1];
                *(__half2*)(y0 + c) = __floats2half2_rn(tanh_acc(acc[s][nt][0] + b0),
                                                        tanh_acc(acc[s][nt][1] + b1v));
                *(__half2*)(y1 + c) = __floats2half2_rn(tanh_acc(acc[s][nt][2] + b0),
                                                        tanh_acc(acc[s][nt][3] + b1v));
            }
        }
    }
}

// ============================================================================
// Per-group multi-head attention (8 heads x 16 dims over 8 agents) + tile x8.
// ============================================================================
__global__ void __launch_bounds__(128)
mha_kernel(const float* __restrict__ AA, const __half* __restrict__ AV,
           float* __restrict__ out)
{
    __shared__ float ks[8][128];
    __shared__ float vs[8][128];
    const int g = blockIdx.x;
    const int j = threadIdx.x;
    const size_t base = (size_t)g * 8 * 128;

    #pragma unroll
    for (int a = 0; a < 8; a++){
        ks[a][j] = AA[base + a * 128 + j];
        vs[a][j] = __half2float(AV[base + a * 128 + j]);
    }
    __syncthreads();

    float q = 0.0f;
    #pragma unroll
    for (int a = 0; a < 8; a++) q += ks[a][j];
    q *= 0.03125f;                            // mean(1/8) * rsqrt(16)

    float s[8];
    #pragma unroll
    for (int a = 0; a < 8; a++){
        float p = q * ks[a][j];
        p += __shfl_xor_sync(0xffffffff, p, 8);
        p += __shfl_xor_sync(0xffffffff, p, 4);
        p += __shfl_xor_sync(0xffffffff, p, 2);
        p += __shfl_xor_sync(0xffffffff, p, 1);
        s[a] = p;
    }
    float mx = s[0];
    #pragma unroll
    for (int a = 1; a < 8; a++) mx = fmaxf(mx, s[a]);
    float wv[8], wsum = 0.0f;
    #pragma unroll
    for (int a = 0; a < 8; a++){ wv[a] = __expf(s[a] - mx); wsum += wv[a]; }
    const float inv = 1.0f / wsum;

    float o = 0.0f;
    #pragma unroll
    for (int a = 0; a < 8; a++) o += wv[a] * vs[a][j];
    o *= inv;

    #pragma unroll
    for (int tt = 0; tt < 8; tt++)
        out[((size_t)(tt * NGRP + g)) * 128 + j] = o;
}

// ============================================================================
extern "C" void kernel_launch(void* const* d_in, const int* in_sizes, int n_in,
                              void* d_out, int out_size)
{
    const float* obs = (const float*)d_in[0];
    const float* eW1 = (const float*)d_in[1];
    const float* eb1 = (const float*)d_in[2];
    const float* eW2 = (const float*)d_in[3];
    const float* eb2 = (const float*)d_in[4];
    const float* vW1 = (const float*)d_in[5];
    const float* vb1 = (const float*)d_in[6];
    const float* vW2 = (const float*)d_in[7];
    const float* vb2 = (const float*)d_in[8];
    const float* aW1 = (const float*)d_in[9];
    const float* ab1 = (const float*)d_in[10];
    const float* aW2 = (const float*)d_in[11];
    const float* ab2 = (const float*)d_in[12];

    float* out = (float*)d_out;                 // multi_head_attention
    float* AA  = out + (size_t)BATCHN * 128;    // agent_attention

    void* pav; cudaGetSymbolAddress(&pav, g_av);
    __half* av_g = (__half*)pav;

    cudaFuncSetAttribute(fused_ev_kernel, cudaFuncAttributeMaxDynamicSharedMemorySize, F_SMEM);
    cudaFuncSetAttribute(agent_kernel,    cudaFuncAttributeMaxDynamicSharedMemorySize, A_SMEM);

    fused_ev_kernel<<<148, 256, F_SMEM>>>(obs, eW1, eb1, eW2, eb2,
                                          vW1, vb1, vW2, vb2, AA);
    agent_kernel<<<148, 256, A_SMEM>>>(AA, aW1, ab1, aW2, ab2, av_g);
    mha_kernel<<<NGRP, 128>>>(AA, av_g, out);
}